// round 8
// baseline (speedup 1.0000x reference)
#include <cuda_runtime.h>

// ============================================================================
// QCNN 8-qubit circuit — exact algebraic reduction to a 3x3 bilinear form.
// Single fused kernel, 256 CTAs x 256 threads, 1 elem/thread (empirically the
// best grid shape), NO block barrier: every warp builds M independently
// (__syncwarp only), final M lives in registers of every lane.
//
// Math (verified R1-R7, rel_err ~1e-7): CNOTs couple only disjoint qubit
// pairs; <Z_0> depends only on the (0,1) 2-qubit subsystem; batch-independent
// params make the 3-layer circuit one fixed 4x4 complex unitary W; with the
// real product input state and double-angle identities:
//     z   = (1, cos x0, sin x0) · M · (1, cos x1, sin x1)^T,  M real 3x3
//     out = sigmoid(weight * z)      (weight folded into M)
// ============================================================================

__global__ void __launch_bounds__(256) qcnn_fused_kernel(
    const float* __restrict__ x,
    const float* __restrict__ params,
    const float* __restrict__ weight,
    float* __restrict__ out,
    int n)
{
    // Per-warp private slices — no cross-warp sharing, no __syncthreads.
    __shared__ float sTrig[8][36];            // 12 trig values x 3 layers
    __shared__ float sWre[8][3][16], sWim[8][3][16];

    const unsigned FULL = 0xFFFFFFFFu;
    int tid  = threadIdx.x;
    int wid  = tid >> 5;
    int lane = tid & 31;
    int i = blockIdx.x * 256 + tid;

    // ---- Issue the batch-data load first; everything overlaps it ----------
    float2 xv = make_float2(0.0f, 0.0f);
    if (i < n)
        xv = *reinterpret_cast<const float2*>(x + (size_t)i * 8);
    float wgt = __ldg(weight);

    // ---- per-warp build of M (lane-parallel, __syncwarp only) -------------
    // 18 angles, one per lane (lanes 0..17); same addresses in all warps ->
    // L1 broadcast after first miss.
    if (lane < 18) {
        int l = lane / 6, rem = lane - l * 6;
        int q = rem / 3, combo = rem - q * 3;
        const float* p = params + l * 24 + q * 3;       // a,b,g contiguous
        float ang;
        if (combo == 0)      ang = 0.5f * p[1];              // b/2
        else if (combo == 1) ang = 0.5f * (p[0] + p[2]);     // (a+g)/2
        else                 ang = 0.5f * (p[0] - p[2]);     // (a-g)/2
        float s, c;
        __sincosf(ang, &s, &c);
        sTrig[wid][(l * 12) + q * 6 + combo * 2 + 0] = c;
        sTrig[wid][(l * 12) + q * 6 + combo * 2 + 1] = s;
    }
    __syncwarp();

    // W chain: lanes 0..15 own element (r,c); CNOT folded via row remap sr.
    int r = (lane >> 2) & 3, c = lane & 3;
    int sr = (r >= 2) ? (5 - r) : r;          // 0,1,3,2
    int q0 = sr >> 1, q1 = sr & 1;

    float wre = 0.0f, wim = 0.0f;
    #pragma unroll
    for (int l = 0; l < 3; l++) {
        const float* T = &sTrig[wid][l * 12];
        float cb0 = T[0],  sb0 = T[1],  cp0 = T[2],  sp0 = T[3];
        float cm0 = T[4],  sm0 = T[5];
        float cb1 = T[6],  sb1 = T[7],  cp1 = T[8],  sp1 = T[9];
        float cm1 = T[10], sm1 = T[11];

        // Row q0 of U0, row q1 of U1:
        //   row0 = [( cb*cp, -cb*sp), (-sb*cm, -sb*sm)]
        //   row1 = [( sb*cm, -sb*sm), ( cb*cp,  cb*sp)]
        float a0r, a0i, a1r, a1i;
        if (q0 == 0) { a0r =  cb0*cp0; a0i = -cb0*sp0; a1r = -sb0*cm0; a1i = -sb0*sm0; }
        else         { a0r =  sb0*cm0; a0i = -sb0*sm0; a1r =  cb0*cp0; a1i =  cb0*sp0; }
        float b0r, b0i, b1r, b1i;
        if (q1 == 0) { b0r =  cb1*cp1; b0i = -cb1*sp1; b1r = -sb1*cm1; b1i = -sb1*sm1; }
        else         { b0r =  sb1*cm1; b0i = -sb1*sm1; b1r =  cb1*cp1; b1i =  cb1*sp1; }

        float Kre[4], Kim[4];                 // K_eff[k] = U0[q0][k>>1]*U1[q1][k&1]
        Kre[0] = a0r*b0r - a0i*b0i;  Kim[0] = a0r*b0i + a0i*b0r;
        Kre[1] = a0r*b1r - a0i*b1i;  Kim[1] = a0r*b1i + a0i*b1r;
        Kre[2] = a1r*b0r - a1i*b0i;  Kim[2] = a1r*b0i + a1i*b0r;
        Kre[3] = a1r*b1r - a1i*b1i;  Kim[3] = a1r*b1i + a1i*b1r;

        if (l == 0) {
            wre = Kre[c];  wim = Kim[c];                 // W_prev = I
        } else {
            if (lane < 16) { sWre[wid][l][lane] = wre; sWim[wid][l][lane] = wim; }
            __syncwarp();
            float ar = 0.0f, ai = 0.0f;
            #pragma unroll
            for (int k = 0; k < 4; k++) {
                float br = sWre[wid][l][k * 4 + c], bi = sWim[wid][l][k * 4 + c];
                ar = fmaf(Kre[k], br, fmaf(-Kim[k], bi, ar));
                ai = fmaf(Kre[k], bi, fmaf( Kim[k], br, ai));
            }
            wre = ar;  wim = ai;
        }
    }

    if (lane < 16) { sWre[wid][0][lane] = wre; sWim[wid][0][lane] = wim; }
    __syncwarp();

    // Lane-parallel S: lane a*4+b computes S[a][b], d=(+,+,-,-).
    {
        int a = (lane >> 2) & 3, b = lane & 3;
        float s_ab = 0.0f;
        #pragma unroll
        for (int rr = 0; rr < 4; rr++) {
            float tt = fmaf(sWre[wid][0][rr * 4 + a], sWre[wid][0][rr * 4 + b],
                            sWim[wid][0][rr * 4 + a] * sWim[wid][0][rr * 4 + b]);
            s_ab += (rr < 2) ? tt : -tt;
        }

        // Broadcast the 10 needed S entries; EVERY lane folds them into M.
        float s00 = __shfl_sync(FULL, s_ab, 0);
        float s11 = __shfl_sync(FULL, s_ab, 5);
        float s22 = __shfl_sync(FULL, s_ab, 10);
        float s33 = __shfl_sync(FULL, s_ab, 15);
        float s01 = __shfl_sync(FULL, s_ab, 1);
        float s23 = __shfl_sync(FULL, s_ab, 11);
        float s02 = __shfl_sync(FULL, s_ab, 2);
        float s13 = __shfl_sync(FULL, s_ab, 7);
        float s03 = __shfl_sync(FULL, s_ab, 3);
        float s12 = __shfl_sync(FULL, s_ab, 6);

        float q4 = 0.25f * wgt, q2 = 0.5f * wgt;
        float m00 = q4 * (s00 + s11 + s22 + s33);
        float m01 = q4 * (s00 - s11 + s22 - s33);
        float m02 = q2 * (s01 + s23);
        float m10 = q4 * (s00 + s11 - s22 - s33);
        float m11 = q4 * (s00 - s11 - s22 + s33);
        float m12 = q2 * (s01 - s23);
        float m20 = q2 * (s02 + s13);
        float m21 = q2 * (s02 - s13);
        float m22 = q2 * (s03 + s12);

        // ---- per-element trig + bilinear form + sigmoid -------------------
        float S0, C0, S1, C1;
        __sincosf(xv.x, &S0, &C0);
        __sincosf(xv.y, &S1, &C1);

        if (i >= n) return;

        float t0 = fmaf(m02, S1, fmaf(m01, C1, m00));
        float t1 = fmaf(m12, S1, fmaf(m11, C1, m10));
        float t2 = fmaf(m22, S1, fmaf(m21, C1, m20));
        float z  = fmaf(S0, t2, fmaf(C0, t1, t0));

        out[i] = __fdividef(1.0f, 1.0f + __expf(-z));
    }
}

extern "C" void kernel_launch(void* const* d_in, const int* in_sizes, int n_in,
                              void* d_out, int out_size) {
    const float* x      = (const float*)d_in[0];   // (65536, 8) fp32
    const float* params = (const float*)d_in[1];   // (3, 8, 3) fp32
    const float* weight = (const float*)d_in[2];   // scalar fp32
    float* out = (float*)d_out;                    // (65536,) fp32

    int n = in_sizes[0] / 8;                       // 65536

    int threads = 256;
    int blocks = (n + threads - 1) / threads;      // 256 blocks
    qcnn_fused_kernel<<<blocks, threads>>>(x, params, weight, out, n);
}

// round 9
// speedup vs baseline: 1.0370x; 1.0370x over previous
#include <cuda_runtime.h>

// ============================================================================
// QCNN 8-qubit circuit — exact algebraic reduction to a 3x3 bilinear form.
// Single fused kernel, 128 CTAs x 512 threads (65536 threads, 1 elem/thread),
// NO block barrier: every warp builds M independently (__syncwarp only),
// final M lives in registers of every lane.
//
// Math (verified R1-R8, rel_err ~1e-7): CNOTs couple only disjoint qubit
// pairs; <Z_0> depends only on the (0,1) 2-qubit subsystem; batch-independent
// params make the 3-layer circuit one fixed 4x4 complex unitary W; with the
// real product input state and double-angle identities:
//     z   = (1, cos x0, sin x0) · M · (1, cos x1, sin x1)^T,  M real 3x3
//     out = sigmoid(weight * z)      (weight folded into M)
// ============================================================================

__global__ void __launch_bounds__(512) qcnn_fused_kernel(
    const float* __restrict__ x,
    const float* __restrict__ params,
    const float* __restrict__ weight,
    float* __restrict__ out,
    int n)
{
    // Per-warp private slices — no cross-warp sharing, no __syncthreads.
    __shared__ float sTrig[16][36];           // 12 trig values x 3 layers
    __shared__ float sWre[16][3][16], sWim[16][3][16];

    const unsigned FULL = 0xFFFFFFFFu;
    int tid  = threadIdx.x;
    int wid  = tid >> 5;
    int lane = tid & 31;
    int i = blockIdx.x * 512 + tid;

    // ---- Issue the batch-data load first; everything overlaps it ----------
    float2 xv = make_float2(0.0f, 0.0f);
    if (i < n)
        xv = *reinterpret_cast<const float2*>(x + (size_t)i * 8);
    float wgt = __ldg(weight);

    // ---- per-element trig, hoisted: runs in the shadow of the build -------
    float S0, C0, S1, C1;
    __sincosf(xv.x, &S0, &C0);
    __sincosf(xv.y, &S1, &C1);

    // ---- per-warp build of M (lane-parallel, __syncwarp only) -------------
    // 18 angles, one per lane (lanes 0..17); same addresses in all warps ->
    // L1 broadcast after first miss.
    if (lane < 18) {
        int l = lane / 6, rem = lane - l * 6;
        int q = rem / 3, combo = rem - q * 3;
        const float* p = params + l * 24 + q * 3;       // a,b,g contiguous
        float ang;
        if (combo == 0)      ang = 0.5f * p[1];              // b/2
        else if (combo == 1) ang = 0.5f * (p[0] + p[2]);     // (a+g)/2
        else                 ang = 0.5f * (p[0] - p[2]);     // (a-g)/2
        float s, c;
        __sincosf(ang, &s, &c);
        sTrig[wid][(l * 12) + q * 6 + combo * 2 + 0] = c;
        sTrig[wid][(l * 12) + q * 6 + combo * 2 + 1] = s;
    }
    __syncwarp();

    // W chain: lanes 0..15 own element (r,c); CNOT folded via row remap sr.
    int r = (lane >> 2) & 3, c = lane & 3;
    int sr = (r >= 2) ? (5 - r) : r;          // 0,1,3,2
    int q0 = sr >> 1, q1 = sr & 1;

    float wre = 0.0f, wim = 0.0f;
    #pragma unroll
    for (int l = 0; l < 3; l++) {
        const float* T = &sTrig[wid][l * 12];
        float cb0 = T[0],  sb0 = T[1],  cp0 = T[2],  sp0 = T[3];
        float cm0 = T[4],  sm0 = T[5];
        float cb1 = T[6],  sb1 = T[7],  cp1 = T[8],  sp1 = T[9];
        float cm1 = T[10], sm1 = T[11];

        // Row q0 of U0, row q1 of U1:
        //   row0 = [( cb*cp, -cb*sp), (-sb*cm, -sb*sm)]
        //   row1 = [( sb*cm, -sb*sm), ( cb*cp,  cb*sp)]
        float a0r, a0i, a1r, a1i;
        if (q0 == 0) { a0r =  cb0*cp0; a0i = -cb0*sp0; a1r = -sb0*cm0; a1i = -sb0*sm0; }
        else         { a0r =  sb0*cm0; a0i = -sb0*sm0; a1r =  cb0*cp0; a1i =  cb0*sp0; }
        float b0r, b0i, b1r, b1i;
        if (q1 == 0) { b0r =  cb1*cp1; b0i = -cb1*sp1; b1r = -sb1*cm1; b1i = -sb1*sm1; }
        else         { b0r =  sb1*cm1; b0i = -sb1*sm1; b1r =  cb1*cp1; b1i =  cb1*sp1; }

        float Kre[4], Kim[4];                 // K_eff[k] = U0[q0][k>>1]*U1[q1][k&1]
        Kre[0] = a0r*b0r - a0i*b0i;  Kim[0] = a0r*b0i + a0i*b0r;
        Kre[1] = a0r*b1r - a0i*b1i;  Kim[1] = a0r*b1i + a0i*b1r;
        Kre[2] = a1r*b0r - a1i*b0i;  Kim[2] = a1r*b0i + a1i*b0r;
        Kre[3] = a1r*b1r - a1i*b1i;  Kim[3] = a1r*b1i + a1i*b1r;

        if (l == 0) {
            wre = Kre[c];  wim = Kim[c];                 // W_prev = I
        } else {
            if (lane < 16) { sWre[wid][l][lane] = wre; sWim[wid][l][lane] = wim; }
            __syncwarp();
            float ar = 0.0f, ai = 0.0f;
            #pragma unroll
            for (int k = 0; k < 4; k++) {
                float br = sWre[wid][l][k * 4 + c], bi = sWim[wid][l][k * 4 + c];
                ar = fmaf(Kre[k], br, fmaf(-Kim[k], bi, ar));
                ai = fmaf(Kre[k], bi, fmaf( Kim[k], br, ai));
            }
            wre = ar;  wim = ai;
        }
    }

    if (lane < 16) { sWre[wid][0][lane] = wre; sWim[wid][0][lane] = wim; }
    __syncwarp();

    // Lane-parallel S: lane a*4+b computes S[a][b], d=(+,+,-,-).
    int a = (lane >> 2) & 3, b = lane & 3;
    float s_ab = 0.0f;
    #pragma unroll
    for (int rr = 0; rr < 4; rr++) {
        float tt = fmaf(sWre[wid][0][rr * 4 + a], sWre[wid][0][rr * 4 + b],
                        sWim[wid][0][rr * 4 + a] * sWim[wid][0][rr * 4 + b]);
        s_ab += (rr < 2) ? tt : -tt;
    }

    // Broadcast the 10 needed S entries; EVERY lane folds them into M.
    float s00 = __shfl_sync(FULL, s_ab, 0);
    float s11 = __shfl_sync(FULL, s_ab, 5);
    float s22 = __shfl_sync(FULL, s_ab, 10);
    float s33 = __shfl_sync(FULL, s_ab, 15);
    float s01 = __shfl_sync(FULL, s_ab, 1);
    float s23 = __shfl_sync(FULL, s_ab, 11);
    float s02 = __shfl_sync(FULL, s_ab, 2);
    float s13 = __shfl_sync(FULL, s_ab, 7);
    float s03 = __shfl_sync(FULL, s_ab, 3);
    float s12 = __shfl_sync(FULL, s_ab, 6);

    float q4 = 0.25f * wgt, q2 = 0.5f * wgt;
    float m00 = q4 * (s00 + s11 + s22 + s33);
    float m01 = q4 * (s00 - s11 + s22 - s33);
    float m02 = q2 * (s01 + s23);
    float m10 = q4 * (s00 + s11 - s22 - s33);
    float m11 = q4 * (s00 - s11 - s22 + s33);
    float m12 = q2 * (s01 - s23);
    float m20 = q2 * (s02 + s13);
    float m21 = q2 * (s02 - s13);
    float m22 = q2 * (s03 + s12);

    if (i >= n) return;

    // z = (1,C0,S0) M (1,C1,S1)^T   (weight already folded into M)
    float t0 = fmaf(m02, S1, fmaf(m01, C1, m00));
    float t1 = fmaf(m12, S1, fmaf(m11, C1, m10));
    float t2 = fmaf(m22, S1, fmaf(m21, C1, m20));
    float z  = fmaf(S0, t2, fmaf(C0, t1, t0));

    out[i] = __fdividef(1.0f, 1.0f + __expf(-z));
}

extern "C" void kernel_launch(void* const* d_in, const int* in_sizes, int n_in,
                              void* d_out, int out_size) {
    const float* x      = (const float*)d_in[0];   // (65536, 8) fp32
    const float* params = (const float*)d_in[1];   // (3, 8, 3) fp32
    const float* weight = (const float*)d_in[2];   // scalar fp32
    float* out = (float*)d_out;                    // (65536,) fp32

    int n = in_sizes[0] / 8;                       // 65536

    int threads = 512;
    int blocks = (n + threads - 1) / threads;      // 128 blocks
    qcnn_fused_kernel<<<blocks, threads>>>(x, params, weight, out, n);
}